// round 12
// baseline (speedup 1.0000x reference)
#include <cuda_runtime.h>
#include <cuda_bf16.h>
#include <cstdint>
#include <cstddef>

#define SEQ   256
#define BATCH 32
#define NVOC  10000
#define NVPAD 10112     // 79 * 128
#define NH    256
#define NG    1024      // NH * 4 gates
#define MTOT  8192      // SEQ * BATCH

// ---------------- scratch (static device globals; no allocation) ----------------
__device__ float    g_gx[(size_t)MTOT * NG];     // layer-0 gate inputs (32 MB)
__device__ unsigned g_cnt;                       // barrier arrival counter
__device__ unsigned g_flag;                      // release flag

// h exchange planes (bf16 hi/lo split, ping-pong parity)
__device__ __nv_bfloat16 g_h1hi[2][BATCH * NH];
__device__ __nv_bfloat16 g_h1lo[2][BATCH * NH];
__device__ __nv_bfloat16 g_h2hi[2][BATCH * NH];
__device__ __nv_bfloat16 g_h2lo[2][BATCH * NH];

// bf16 split buffers for tensor-core decoder
__device__ __nv_bfloat16 g_Ahi[(size_t)MTOT * NH];
__device__ __nv_bfloat16 g_Alo[(size_t)MTOT * NH];
__device__ __nv_bfloat16 g_Whi[(size_t)NVPAD * NH];
__device__ __nv_bfloat16 g_Wlo[(size_t)NVPAD * NH];

// ---------------- init: zero h planes + barrier ----------------
__global__ void init_state() {
    int t = blockIdx.x * blockDim.x + threadIdx.x;
    int nthr = gridDim.x * blockDim.x;
    uint32_t* p1h = (uint32_t*)g_h1hi; uint32_t* p1l = (uint32_t*)g_h1lo;
    uint32_t* p2h = (uint32_t*)g_h2hi; uint32_t* p2l = (uint32_t*)g_h2lo;
    for (int i = t; i < 2 * BATCH * NH / 2; i += nthr) {
        p1h[i] = 0u; p1l[i] = 0u; p2h[i] = 0u; p2l[i] = 0u;
    }
    if (t == 0) { g_cnt = 0u; g_flag = 0u; }
}

// ---------------- gx GEMM (layer 0 only, fp32 — proven) ----------------
__global__ __launch_bounds__(256) void gemm_gx(
    const float* __restrict__ embed_W,
    const int*   __restrict__ tokens,
    const float* __restrict__ Wx,      // [256][1024]
    const float* __restrict__ bias)    // [1024]
{
    __shared__ float As[16][132];
    __shared__ float Bs[16][132];

    const int m0 = blockIdx.y * 128;
    const int n0 = blockIdx.x * 128;
    const int t  = threadIdx.x;
    const int tx = t & 15;
    const int ty = t >> 4;

    const int r0 = t >> 2;
    const int r1 = r0 + 64;
    const int kq = (t & 3) * 4;
    const float* ap0 = embed_W + (size_t)tokens[m0 + r0] * NH;
    const float* ap1 = embed_W + (size_t)tokens[m0 + r1] * NH;

    float acc[8][8];
    #pragma unroll
    for (int i = 0; i < 8; i++)
        #pragma unroll
        for (int j = 0; j < 8; j++) acc[i][j] = 0.f;

    for (int k0 = 0; k0 < NH; k0 += 16) {
        {
            float4 v0 = *(const float4*)(ap0 + k0 + kq);
            float4 v1 = *(const float4*)(ap1 + k0 + kq);
            As[kq + 0][r0] = v0.x; As[kq + 1][r0] = v0.y;
            As[kq + 2][r0] = v0.z; As[kq + 3][r0] = v0.w;
            As[kq + 0][r1] = v1.x; As[kq + 1][r1] = v1.y;
            As[kq + 2][r1] = v1.z; As[kq + 3][r1] = v1.w;
        }
        #pragma unroll
        for (int i = 0; i < 2; i++) {
            int lin = t + i * 256;
            int kk  = lin >> 5;
            int nq  = (lin & 31) * 4;
            *(float4*)&Bs[kk][nq] = *(const float4*)(Wx + (size_t)(k0 + kk) * NG + n0 + nq);
        }
        __syncthreads();
        #pragma unroll
        for (int kk = 0; kk < 16; kk++) {
            float a[8], b[8];
            *(float4*)&a[0] = *(const float4*)&As[kk][ty * 8];
            *(float4*)&a[4] = *(const float4*)&As[kk][ty * 8 + 4];
            *(float4*)&b[0] = *(const float4*)&Bs[kk][tx * 8];
            *(float4*)&b[4] = *(const float4*)&Bs[kk][tx * 8 + 4];
            #pragma unroll
            for (int i = 0; i < 8; i++)
                #pragma unroll
                for (int j = 0; j < 8; j++)
                    acc[i][j] += a[i] * b[j];
        }
        __syncthreads();
    }

    #pragma unroll
    for (int i = 0; i < 8; i++) {
        size_t m = (size_t)(m0 + ty * 8 + i);
        float* op = g_gx + m * NG + n0 + tx * 8;
        const float* bp = bias + n0 + tx * 8;
        #pragma unroll
        for (int j = 0; j < 8; j++) op[j] = acc[i][j] + bp[j];
    }
}

// ---------------- MMA macros (decoder-verified) ----------------
#define LDM_A(r0,r1,r2,r3,addr) \
    asm volatile("ldmatrix.sync.aligned.m8n8.x4.shared.b16 {%0,%1,%2,%3}, [%4];" \
        : "=r"(r0), "=r"(r1), "=r"(r2), "=r"(r3) : "r"(addr))

#define MMA_BF16(c, a, b) \
    asm volatile("mma.sync.aligned.m16n8k16.row.col.f32.bf16.bf16.f32 " \
        "{%0,%1,%2,%3}, {%4,%5,%6,%7}, {%8,%9}, {%0,%1,%2,%3};" \
        : "+f"((c)[0]), "+f"((c)[1]), "+f"((c)[2]), "+f"((c)[3]) \
        : "r"((a)[0]), "r"((a)[1]), "r"((a)[2]), "r"((a)[3]), "r"((b)[0]), "r"((b)[1]))

// ---------------- fused 2-layer LSTM recurrence (tensor-core core, 64 CTAs x 16 cols) ----------------
// 64 CTAs x 256 threads, 257 rounds. Round r: layer0 step r, layer1 step r-1.
// CTA owns 16 gate-cols. B stack (resident): [W0(16); Wx1(16); Wh1(16)] rows x 256 K,
// bf16 hi/lo, pitch 264. A tiles per round: h1/h2 hi/lo 32x256. 8 warps split K (32 each).
// Thread (b = t>>3, c = t&7) handles cols c and c+8.
#define RPITCH 264                               // bf16 units per row
#define PLANE_A (32 * RPITCH * 2)                // 16896 B per A plane
#define PLANE_BB (48 * RPITCH * 2)               // 25344 B per B plane
#define OFF_BHI 0
#define OFF_BLO PLANE_BB
#define OFF_A   (2 * PLANE_BB)
#define OFF_PART (OFF_A + 4 * PLANE_A)           // fp32 partials [2][32][16][8]
#define RS_BYTES (OFF_PART + 2 * 32 * 16 * 8 * 4)   // 183,808 B

__global__ __launch_bounds__(256, 1) void fused_rnn(
    const float* __restrict__ Wh0,   // [256][1024]
    const float* __restrict__ Wx1,   // [256][1024]
    const float* __restrict__ Wh1,   // [256][1024]
    const float* __restrict__ b1,    // [1024]
    float*       __restrict__ h1_out,
    float*       __restrict__ h2_out)
{
    extern __shared__ char smc[];
    __nv_bfloat16* sBhi = (__nv_bfloat16*)(smc + OFF_BHI);
    __nv_bfloat16* sBlo = (__nv_bfloat16*)(smc + OFF_BLO);
    float*         sPart = (float*)(smc + OFF_PART);

    const int t    = threadIdx.x;
    const int warp = t >> 5;
    const int lane = t & 31;
    const int kg0  = blockIdx.x * 16;
    const int c    = t & 7;
    const int b    = t >> 3;
    const int kA   = (kg0 + c) >> 2;          // owned cell, col group A
    const int kB   = (kg0 + c + 8) >> 2;      // owned cell, col group B
    const bool owner = (t & 3) == 0;
    const unsigned base = lane & ~3u;
    const unsigned grid = gridDim.x;

    // ---- load weight stack (hi/lo split), resident for whole kernel ----
    for (int idx = t; idx < 3 * 16 * NH; idx += 256) {
        int m   = idx >> 12;          // 0=Wh0, 1=Wx1, 2=Wh1
        int rem = idx & 4095;
        int j   = rem >> 8;           // col within matrix (0..15)
        int kk  = rem & 255;
        const float* src = (m == 0) ? Wh0 : ((m == 1) ? Wx1 : Wh1);
        float x = src[(size_t)kk * NG + kg0 + j];
        __nv_bfloat16 hi = __float2bfloat16_rn(x);
        int row = m * 16 + j;
        sBhi[row * RPITCH + kk] = hi;
        sBlo[row * RPITCH + kk] = __float2bfloat16_rn(x - __bfloat162float(hi));
    }
    const float b1vA = b1[kg0 + c];
    const float b1vB = b1[kg0 + c + 8];

    const uint32_t usm  = (uint32_t)__cvta_generic_to_shared(smc);
    const uint32_t uBhi = usm + OFF_BHI;
    const uint32_t uBlo = usm + OFF_BLO;
    const uint32_t uA0  = usm + OFF_A;              // h1hi
    const uint32_t uA1  = uA0 + PLANE_A;            // h1lo
    const uint32_t uA2  = uA1 + PLANE_A;            // h2hi
    const uint32_t uA3  = uA2 + PLANE_A;            // h2lo

    const int a_row = lane & 15;
    const int a_k   = (lane >> 4) * 8;
    const int b_row = (lane & 7) + ((lane >> 4) << 3);
    const int b_k   = ((lane >> 3) & 1) * 8;
    const int k0w   = warp * 32;

    float c1A = 0.f, c1B = 0.f, c2A = 0.f, c2B = 0.f;

    for (int r = 0; r <= SEQ; r++) {
        // prefetch gx (independent of barrier)
        int s0 = (r < SEQ) ? r : SEQ - 1;
        const float* gxp = g_gx + (size_t)s0 * BATCH * NG + (size_t)b * NG + kg0;
        float gxA = gxp[c];
        float gxB = gxp[c + 8];

        // ---- wait for previous round's h publication ----
        if (r > 0 && t == 0) {
            while (*(volatile unsigned*)&g_flag < (unsigned)r) { }
            __threadfence();
        }
        __syncthreads();

        // ---- refill A planes (bf16, parity r&1) ----
        {
            const __nv_bfloat16* gp[4] = { g_h1hi[r & 1], g_h1lo[r & 1],
                                           g_h2hi[r & 1], g_h2lo[r & 1] };
            #pragma unroll
            for (int p = 0; p < 4; p++) {
                __nv_bfloat16* sAp = (__nv_bfloat16*)(smc + OFF_A + p * PLANE_A);
                #pragma unroll
                for (int i = 0; i < 4; i++) {
                    int cc = t + i * 256;            // 0..1023 (16B chunks)
                    int row = cc >> 5, c16 = cc & 31;
                    *(uint4*)&sAp[row * RPITCH + c16 * 8] =
                        __ldcg((const uint4*)(gp[p] + row * NH + c16 * 8));
                }
            }
        }
        __syncthreads();

        // ---- tensor-core z: warp handles K in [warp*32, warp*32+32) ----
        float z0a[2][2][4], z1a[2][2][4];
        #pragma unroll
        for (int m = 0; m < 2; m++)
            #pragma unroll
            for (int n = 0; n < 2; n++)
                #pragma unroll
                for (int q = 0; q < 4; q++) { z0a[m][n][q] = 0.f; z1a[m][n][q] = 0.f; }

        #pragma unroll
        for (int kc = 0; kc < 2; kc++) {
            const int k0 = k0w + kc * 16;
            uint32_t ah1h[2][4], ah1l[2][4], ah2h[2][4], ah2l[2][4];
            #pragma unroll
            for (int m = 0; m < 2; m++) {
                uint32_t ro = (uint32_t)((m * 16 + a_row) * RPITCH + k0 + a_k) * 2;
                LDM_A(ah1h[m][0], ah1h[m][1], ah1h[m][2], ah1h[m][3], uA0 + ro);
                LDM_A(ah1l[m][0], ah1l[m][1], ah1l[m][2], ah1l[m][3], uA1 + ro);
                LDM_A(ah2h[m][0], ah2h[m][1], ah2h[m][2], ah2h[m][3], uA2 + ro);
                LDM_A(ah2l[m][0], ah2l[m][1], ah2l[m][2], ah2l[m][3], uA3 + ro);
            }
            // B frags: one x4 per matrix per precision -> two n8 frags each
            uint32_t w0h[2][2], wxh[2][2], w1h[2][2];
            uint32_t w0l[2][2], wxl[2][2], w1l[2][2];
            {
                uint32_t r0, r1, r2, r3;
                uint32_t ro0 = (uint32_t)(( 0 + b_row) * RPITCH + k0 + b_k) * 2;
                uint32_t ro1 = (uint32_t)((16 + b_row) * RPITCH + k0 + b_k) * 2;
                uint32_t ro2 = (uint32_t)((32 + b_row) * RPITCH + k0 + b_k) * 2;
                LDM_A(r0, r1, r2, r3, uBhi + ro0);
                w0h[0][0] = r0; w0h[0][1] = r1; w0h[1][0] = r2; w0h[1][1] = r3;
                LDM_A(r0, r1, r2, r3, uBlo + ro0);
                w0l[0][0] = r0; w0l[0][1] = r1; w0l[1][0] = r2; w0l[1][1] = r3;
                LDM_A(r0, r1, r2, r3, uBhi + ro1);
                wxh[0][0] = r0; wxh[0][1] = r1; wxh[1][0] = r2; wxh[1][1] = r3;
                LDM_A(r0, r1, r2, r3, uBlo + ro1);
                wxl[0][0] = r0; wxl[0][1] = r1; wxl[1][0] = r2; wxl[1][1] = r3;
                LDM_A(r0, r1, r2, r3, uBhi + ro2);
                w1h[0][0] = r0; w1h[0][1] = r1; w1h[1][0] = r2; w1h[1][1] = r3;
                LDM_A(r0, r1, r2, r3, uBlo + ro2);
                w1l[0][0] = r0; w1l[0][1] = r1; w1l[1][0] = r2; w1l[1][1] = r3;
            }
            #pragma unroll
            for (int m = 0; m < 2; m++)
                #pragma unroll
                for (int n = 0; n < 2; n++) {
                    // z0 = h1 . W0   (split-bf16, 3 products)
                    MMA_BF16(z0a[m][n], ah1h[m], w0h[n]);
                    MMA_BF16(z0a[m][n], ah1h[m], w0l[n]);
                    MMA_BF16(z0a[m][n], ah1l[m], w0h[n]);
                    // z1 = h1 . Wx1 + h2 . Wh1
                    MMA_BF16(z1a[m][n], ah1h[m], wxh[n]);
                    MMA_BF16(z1a[m][n], ah1h[m], wxl[n]);
                    MMA_BF16(z1a[m][n], ah1l[m], wxh[n]);
                    MMA_BF16(z1a[m][n], ah2h[m], w1h[n]);
                    MMA_BF16(z1a[m][n], ah2h[m], w1l[n]);
                    MMA_BF16(z1a[m][n], ah2l[m], w1h[n]);
                }
        }

        // ---- store per-warp partials: part[zt][row][col][warp], col dim 16 ----
        {
            const int g  = lane >> 2;
            const int t4 = lane & 3;
            #pragma unroll
            for (int m = 0; m < 2; m++)
                #pragma unroll
                for (int n = 0; n < 2; n++) {
                    int rowb = m * 16 + g;
                    int col  = n * 8 + t4 * 2;
                    float* p0 = sPart + (0 * 32 + rowb) * 128 + col * 8 + warp;
                    float* p1 = sPart + (1 * 32 + rowb) * 128 + col * 8 + warp;
                    p0[0] = z0a[m][n][0]; p0[8] = z0a[m][n][1];
                    p0[1024] = z0a[m][n][2]; p0[1032] = z0a[m][n][3];
                    p1[0] = z1a[m][n][0]; p1[8] = z1a[m][n][1];
                    p1[1024] = z1a[m][n][2]; p1[1032] = z1a[m][n][3];
                }
        }
        __syncthreads();

        // ---- reduce 8 K-partials for cols c and c+8; add gx / bias ----
        float z0A = gxA, z0B = gxB, z1A = b1vA, z1B = b1vB;
        {
            const float* r0 = sPart + b * 128;
            const float* r1 = sPart + (32 + b) * 128;
            #pragma unroll
            for (int h = 0; h < 2; h++) {
                const float* q0 = r0 + (c + h * 8) * 8;
                const float* q1 = r1 + (c + h * 8) * 8;
                float4 v0 = *(const float4*)q0, v1 = *(const float4*)(q0 + 4);
                float4 u0 = *(const float4*)q1, u1 = *(const float4*)(q1 + 4);
                float s0 = v0.x + v0.y + v0.z + v0.w + v1.x + v1.y + v1.z + v1.w;
                float s1 = u0.x + u0.y + u0.z + u0.w + u1.x + u1.y + u1.z + u1.w;
                if (h == 0) { z0A += s0; z1A += s1; }
                else        { z0B += s0; z1B += s1; }
            }
        }

        // ---- gate gather (4 values x 4 gates) ----
        float ziA0 = __shfl_sync(0xffffffffu, z0A, base + 0);
        float zfA0 = __shfl_sync(0xffffffffu, z0A, base + 1);
        float zoA0 = __shfl_sync(0xffffffffu, z0A, base + 2);
        float zgA0 = __shfl_sync(0xffffffffu, z0A, base + 3);
        float ziB0 = __shfl_sync(0xffffffffu, z0B, base + 0);
        float zfB0 = __shfl_sync(0xffffffffu, z0B, base + 1);
        float zoB0 = __shfl_sync(0xffffffffu, z0B, base + 2);
        float zgB0 = __shfl_sync(0xffffffffu, z0B, base + 3);
        float ziA1 = __shfl_sync(0xffffffffu, z1A, base + 0);
        float zfA1 = __shfl_sync(0xffffffffu, z1A, base + 1);
        float zoA1 = __shfl_sync(0xffffffffu, z1A, base + 2);
        float zgA1 = __shfl_sync(0xffffffffu, z1A, base + 3);
        float ziB1 = __shfl_sync(0xffffffffu, z1B, base + 0);
        float zfB1 = __shfl_sync(0xffffffffu, z1B, base + 1);
        float zoB1 = __shfl_sync(0xffffffffu, z1B, base + 2);
        float zgB1 = __shfl_sync(0xffffffffu, z1B, base + 3);

        if (owner) {
            int np = (r + 1) & 1;
            if (r < SEQ) {      // layer 0 step r (cells kA, kB)
                float ig = 1.f / (1.f + __expf(-ziA0));
                float fg = 1.f / (1.f + __expf(-zfA0));
                float og = 1.f / (1.f + __expf(-zoA0));
                float gg = tanhf(zgA0);
                c1A = fg * c1A + ig * gg;
                float hnA = og * tanhf(c1A);
                ig = 1.f / (1.f + __expf(-ziB0));
                fg = 1.f / (1.f + __expf(-zfB0));
                og = 1.f / (1.f + __expf(-zoB0));
                gg = tanhf(zgB0);
                c1B = fg * c1B + ig * gg;
                float hnB = og * tanhf(c1B);
                __nv_bfloat16 ha = __float2bfloat16_rn(hnA);
                __nv_bfloat16 hb = __float2bfloat16_rn(hnB);
                g_h1hi[np][b * NH + kA] = ha;
                g_h1lo[np][b * NH + kA] = __float2bfloat16_rn(hnA - __bfloat162float(ha));
                g_h1hi[np][b * NH + kB] = hb;
                g_h1lo[np][b * NH + kB] = __float2bfloat16_rn(hnB - __bfloat162float(hb));
                if (r == SEQ - 1) { h1_out[b * NH + kA] = hnA; h1_out[b * NH + kB] = hnB; }
            }
            if (r >= 1) {       // layer 1 step r-1 (cells kA, kB)
                int s1 = r - 1;
                size_t m = (size_t)s1 * BATCH + b;
                float ig = 1.f / (1.f + __expf(-ziA1));
                float fg = 1.f / (1.f + __expf(-zfA1));
                float og = 1.f / (1.f + __expf(-zoA1));
                float gg = tanhf(zgA1);
                c2A = fg * c2A + ig * gg;
                float hnA = og * tanhf(c2A);
                ig = 1.f / (1.f + __expf(-ziB1));
                fg = 1.f / (1.f + __expf(-zfB1));
                og = 1.f / (1.f + __expf(-zoB1));
                gg = tanhf(zgB1);
                c2B = fg * c2B + ig * gg;
                float hnB = og * tanhf(c2B);
                __nv_bfloat16 ha = __float2bfloat16_rn(hnA);
                __nv_bfloat16 la = __float2bfloat16_rn(hnA - __bfloat162float(ha));
                __nv_bfloat16 hb = __float2bfloat16_rn(hnB);
                __nv_bfloat16 lb = __float2bfloat16_rn(hnB - __bfloat162float(hb));
                g_h2hi[np][b * NH + kA] = ha;
                g_h2lo[np][b * NH + kA] = la;
                g_h2hi[np][b * NH + kB] = hb;
                g_h2lo[np][b * NH + kB] = lb;
                g_Ahi[m * NH + kA] = ha;
                g_Alo[m * NH + kA] = la;
                g_Ahi[m * NH + kB] = hb;
                g_Alo[m * NH + kB] = lb;
                if (s1 == SEQ - 1) { h2_out[b * NH + kA] = hnA; h2_out[b * NH + kB] = hnB; }
            }
        }

        // ---- arrive (round-4 protocol) ----
        if (r < SEQ) {
            __syncthreads();
            if (t == 0) {
                __threadfence();
                unsigned old = atomicAdd(&g_cnt, 1u);
                if (old == (unsigned)r * grid + grid - 1u)
                    atomicExch(&g_flag, (unsigned)(r + 1));
            }
        }
    }
}

// ---------------- bf16 split of decoder weights (scalar — proven) ----------------
__global__ __launch_bounds__(256) void conv_W(const float* __restrict__ W) {
    int i = blockIdx.x * blockDim.x + threadIdx.x;
    if (i < NVPAD * NH) {
        int v = i >> 8;
        float x = (v < NVOC) ? W[(size_t)v * NH + (i & 255)] : 0.f;
        __nv_bfloat16 hi = __float2bfloat16_rn(x);
        g_Whi[i] = hi;
        g_Wlo[i] = __float2bfloat16_rn(x - __bfloat162float(hi));
    }
}

// ---------------- tensor-core decoder GEMM (split-bf16; 2 CTAs/SM) ----------------
__global__ __launch_bounds__(256, 2) void gemm_dec_tc(
    const float* __restrict__ bias,
    float*       __restrict__ out)
{
    __shared__ __nv_bfloat16 sAhi[128][40];
    __shared__ __nv_bfloat16 sAlo[128][40];
    __shared__ __nv_bfloat16 sBhi[128][40];
    __shared__ __nv_bfloat16 sBlo[128][40];

    const int t    = threadIdx.x;
    const int warp = t >> 5;
    const int lane = t & 31;
    const int m0   = blockIdx.y * 128;
    const int n0   = blockIdx.x * 128;
    const int wm   = warp >> 2;
    const int wn   = warp & 3;

    float acc[4][4][4];
    #pragma unroll
    for (int i = 0; i < 4; i++)
        #pragma unroll
        for (int j = 0; j < 4; j++)
            #pragma unroll
            for (int q = 0; q < 4; q++) acc[i][j][q] = 0.f;

    const uint32_t bAhi = (uint32_t)__cvta_generic_to_shared(&sAhi[0][0]);
    const uint32_t bAlo = (uint32_t)__cvta_generic_to_shared(&sAlo[0][0]);
    const uint32_t bBhi = (uint32_t)__cvta_generic_to_shared(&sBhi[0][0]);
    const uint32_t bBlo = (uint32_t)__cvta_generic_to_shared(&sBlo[0][0]);

    const int a_row = (lane & 15);
    const int a_k   = (lane >> 4) * 8;
    const int b_row = (lane & 7) + ((lane >> 4) << 3);
    const int b_k   = ((lane >> 3) & 1) * 8;

    for (int kc = 0; kc < 8; kc++) {
        const int k0 = kc * 32;
        #pragma unroll
        for (int h = 0; h < 2; h++) {
            int cc  = t + h * 256;
            int row = cc >> 2;
            int q   = cc & 3;
            size_t gA = (size_t)(m0 + row) * NH + k0 + q * 8;
            size_t gB = (size_t)(n0 + row) * NH + k0 + q * 8;
            *(uint4*)&sAhi[row][q * 8] = *(const uint4*)(g_Ahi + gA);
            *(uint4*)&sAlo[row][q * 8] = *(const uint4*)(g_Alo + gA);
            *(uint4*)&sBhi[row][q * 8] = *(const uint4*)(g_Whi + gB);
            *(uint4*)&sBlo[row][q * 8] = *(const uint4*)(g_Wlo + gB);
        }
        __syncthreads();

        #pragma unroll
        for (int ks = 0; ks < 32; ks += 16) {
            uint32_t af[4][4];
            uint32_t bh[4][2], bl[4][2];

            #pragma unroll
            for (int nh = 0; nh < 2; nh++) {
                int roff = (wn * 32 + nh * 16 + b_row) * 40 + ks + b_k;
                uint32_t r0, r1, r2, r3;
                LDM_A(r0, r1, r2, r3, bBhi + roff * 2);
                bh[2*nh][0] = r0; bh[2*nh][1] = r1;
                bh[2*nh+1][0] = r2; bh[2*nh+1][1] = r3;
                LDM_A(r0, r1, r2, r3, bBlo + roff * 2);
                bl[2*nh][0] = r0; bl[2*nh][1] = r1;
                bl[2*nh+1][0] = r2; bl[2*nh+1][1] = r3;
            }
            #pragma unroll
            for (int mi = 0; mi < 4; mi++) {
                int roff = (wm * 64 + mi * 16 + a_row) * 40 + ks + a_k;
                LDM_A(af[mi][0], af[mi][1], af[mi][2], af[mi][3], bAhi + roff * 2);
            }
            #pragma unroll
            for (int mi = 0; mi < 4; mi++)
                #pragma unroll
                for (int ni = 0; ni < 4; ni++) {
                    MMA_BF16(acc[mi][ni], af[mi], bh[ni]);
                    MMA_BF16(acc[mi][ni], af[mi], bl[ni]);
                }
            #pragma unroll
            for (int mi = 0; mi < 4; mi++) {
                int roff = (wm * 64 + mi * 16 + a_row) * 40 + ks + a_k;
                LDM_A(af[mi][0], af[mi][1], af[mi][2], af[mi][3], bAlo + roff * 2);
            }
            #pragma unroll
            for (int mi = 0; mi < 4; mi++)
                #pragma unroll
                for (int ni = 0; ni < 4; ni++)
                    MMA_BF16(acc[mi][ni], af[mi], bh[ni]);
        }
        __syncthreads();
    }

    const int g  = lane >> 2;
    const int t4 = lane & 3;
    #pragma unroll
    for (int mi = 0; mi < 4; mi++) {
        #pragma unroll
        for (int ni = 0; ni < 4; ni++) {
            int col = n0 + wn * 32 + ni * 8 + t4 * 2;
            if (col < NVOC) {
                float b0 = bias[col], b1 = bias[col + 1];
                int row0 = m0 + wm * 64 + mi * 16 + g;
                float2 v0 = make_float2(acc[mi][ni][0] + b0, acc[mi][ni][1] + b1);
                float2 v1 = make_float2(acc[mi][ni][2] + b0, acc[mi][ni][3] + b1);
                *(float2*)(out + (size_t)row0 * NVOC + col) = v0;
                *(float2*)(out + (size_t)(row0 + 8) * NVOC + col) = v1;
            }
        }
    }
}

// ---------------- launch ----------------
extern "C" void kernel_launch(void* const* d_in, const int* in_sizes, int n_in,
                              void* d_out, int out_size) {
    const int*   tokens  = (const int*)  d_in[0];
    const float* embed_W = (const float*)d_in[1];
    const float* Wx0     = (const float*)d_in[2];
    const float* Wh0     = (const float*)d_in[3];
    const float* b0      = (const float*)d_in[4];
    const float* Wx1     = (const float*)d_in[5];
    const float* Wh1     = (const float*)d_in[6];
    const float* b1      = (const float*)d_in[7];
    const float* dec_W   = (const float*)d_in[8];
    const float* dec_b   = (const float*)d_in[9];
    (void)in_sizes; (void)n_in;

    float* out    = (float*)d_out;
    float* h1_out = out + (size_t)out_size - 2 * BATCH * NH;
    float* h2_out = out + (size_t)out_size - 1 * BATCH * NH;

    static bool attr_done = false;
    if (!attr_done) {
        cudaFuncSetAttribute(fused_rnn, cudaFuncAttributeMaxDynamicSharedMemorySize, RS_BYTES);
        attr_done = true;
    }

    conv_W<<<(NVPAD * NH + 255) / 256, 256>>>(dec_W);
    init_state<<<16, 256>>>();
    gemm_gx<<<dim3(8, 64), 256>>>(embed_W, tokens, Wx0, b0);
    fused_rnn<<<64, 256, RS_BYTES>>>(Wh0, Wx1, Wh1, b1, h1_out, h2_out);
    gemm_dec_tc<<<dim3(79, 64), 256>>>(dec_b, out);
}

// round 13
// speedup vs baseline: 1.2715x; 1.2715x over previous
#include <cuda_runtime.h>
#include <cuda_bf16.h>
#include <cstdint>
#include <cstddef>

#define SEQ   256
#define BATCH 32
#define NVOC  10000
#define NVPAD 10112     // 79 * 128
#define NH    256
#define NG    1024      // NH * 4 gates
#define MTOT  8192      // SEQ * BATCH

// ---------------- scratch (static device globals; no allocation) ----------------
__device__ float    g_gx[(size_t)MTOT * NG];     // layer-0 gate inputs (32 MB)
__device__ unsigned g_cnt;                       // barrier arrival counter
__device__ unsigned g_flag;                      // release flag

// h exchange planes (bf16 hi/lo split, ping-pong parity)
__device__ __nv_bfloat16 g_h1hi[2][BATCH * NH];
__device__ __nv_bfloat16 g_h1lo[2][BATCH * NH];
__device__ __nv_bfloat16 g_h2hi[2][BATCH * NH];
__device__ __nv_bfloat16 g_h2lo[2][BATCH * NH];

// bf16 split buffers for tensor-core decoder
__device__ __nv_bfloat16 g_Ahi[(size_t)MTOT * NH];
__device__ __nv_bfloat16 g_Alo[(size_t)MTOT * NH];
__device__ __nv_bfloat16 g_Whi[(size_t)NVPAD * NH];
__device__ __nv_bfloat16 g_Wlo[(size_t)NVPAD * NH];

// ---------------- init: zero h planes + barrier ----------------
__global__ void init_state() {
    int t = blockIdx.x * blockDim.x + threadIdx.x;
    int nthr = gridDim.x * blockDim.x;
    uint32_t* p1h = (uint32_t*)g_h1hi; uint32_t* p1l = (uint32_t*)g_h1lo;
    uint32_t* p2h = (uint32_t*)g_h2hi; uint32_t* p2l = (uint32_t*)g_h2lo;
    for (int i = t; i < 2 * BATCH * NH / 2; i += nthr) {
        p1h[i] = 0u; p1l[i] = 0u; p2h[i] = 0u; p2l[i] = 0u;
    }
    if (t == 0) { g_cnt = 0u; g_flag = 0u; }
}

// ---------------- gx GEMM (layer 0 only, fp32 — proven) ----------------
__global__ __launch_bounds__(256) void gemm_gx(
    const float* __restrict__ embed_W,
    const int*   __restrict__ tokens,
    const float* __restrict__ Wx,      // [256][1024]
    const float* __restrict__ bias)    // [1024]
{
    __shared__ float As[16][132];
    __shared__ float Bs[16][132];

    const int m0 = blockIdx.y * 128;
    const int n0 = blockIdx.x * 128;
    const int t  = threadIdx.x;
    const int tx = t & 15;
    const int ty = t >> 4;

    const int r0 = t >> 2;
    const int r1 = r0 + 64;
    const int kq = (t & 3) * 4;
    const float* ap0 = embed_W + (size_t)tokens[m0 + r0] * NH;
    const float* ap1 = embed_W + (size_t)tokens[m0 + r1] * NH;

    float acc[8][8];
    #pragma unroll
    for (int i = 0; i < 8; i++)
        #pragma unroll
        for (int j = 0; j < 8; j++) acc[i][j] = 0.f;

    for (int k0 = 0; k0 < NH; k0 += 16) {
        {
            float4 v0 = *(const float4*)(ap0 + k0 + kq);
            float4 v1 = *(const float4*)(ap1 + k0 + kq);
            As[kq + 0][r0] = v0.x; As[kq + 1][r0] = v0.y;
            As[kq + 2][r0] = v0.z; As[kq + 3][r0] = v0.w;
            As[kq + 0][r1] = v1.x; As[kq + 1][r1] = v1.y;
            As[kq + 2][r1] = v1.z; As[kq + 3][r1] = v1.w;
        }
        #pragma unroll
        for (int i = 0; i < 2; i++) {
            int lin = t + i * 256;
            int kk  = lin >> 5;
            int nq  = (lin & 31) * 4;
            *(float4*)&Bs[kk][nq] = *(const float4*)(Wx + (size_t)(k0 + kk) * NG + n0 + nq);
        }
        __syncthreads();
        #pragma unroll
        for (int kk = 0; kk < 16; kk++) {
            float a[8], b[8];
            *(float4*)&a[0] = *(const float4*)&As[kk][ty * 8];
            *(float4*)&a[4] = *(const float4*)&As[kk][ty * 8 + 4];
            *(float4*)&b[0] = *(const float4*)&Bs[kk][tx * 8];
            *(float4*)&b[4] = *(const float4*)&Bs[kk][tx * 8 + 4];
            #pragma unroll
            for (int i = 0; i < 8; i++)
                #pragma unroll
                for (int j = 0; j < 8; j++)
                    acc[i][j] += a[i] * b[j];
        }
        __syncthreads();
    }

    #pragma unroll
    for (int i = 0; i < 8; i++) {
        size_t m = (size_t)(m0 + ty * 8 + i);
        float* op = g_gx + m * NG + n0 + tx * 8;
        const float* bp = bias + n0 + tx * 8;
        #pragma unroll
        for (int j = 0; j < 8; j++) op[j] = acc[i][j] + bp[j];
    }
}

// ---------------- MMA / async-copy macros ----------------
#define LDM_A(r0,r1,r2,r3,addr) \
    asm volatile("ldmatrix.sync.aligned.m8n8.x4.shared.b16 {%0,%1,%2,%3}, [%4];" \
        : "=r"(r0), "=r"(r1), "=r"(r2), "=r"(r3) : "r"(addr))

#define MMA_BF16(c, a, b) \
    asm volatile("mma.sync.aligned.m16n8k16.row.col.f32.bf16.bf16.f32 " \
        "{%0,%1,%2,%3}, {%4,%5,%6,%7}, {%8,%9}, {%0,%1,%2,%3};" \
        : "+f"((c)[0]), "+f"((c)[1]), "+f"((c)[2]), "+f"((c)[3]) \
        : "r"((a)[0]), "r"((a)[1]), "r"((a)[2]), "r"((a)[3]), "r"((b)[0]), "r"((b)[1]))

#define CP_ASYNC16(dst, src) \
    asm volatile("cp.async.ca.shared.global [%0],[%1],16;" :: "r"(dst), "l"(src))
#define CP_COMMIT() asm volatile("cp.async.commit_group;" ::: "memory")
#define CP_WAIT1()  asm volatile("cp.async.wait_group 1;" ::: "memory")
#define CP_WAIT0()  asm volatile("cp.async.wait_group 0;" ::: "memory")

// ---------------- fused 2-layer LSTM recurrence (round-10 kernel, best measured) ----------------
// 128 CTAs x 256 threads, 257 rounds. Round r: layer0 step r, layer1 step r-1.
#define RPITCH 264                              // bf16 units per row
#define PLANE_B (32 * RPITCH * 2)               // 16896 bytes per bf16 plane
#define OFF_BHI 0
#define OFF_BLO PLANE_B
#define OFF_A   (2 * PLANE_B)                   // 4 A planes follow
#define OFF_PART (6 * PLANE_B)                  // fp32 partials [2][32][8][8]
#define RS_BYTES (OFF_PART + 2 * 32 * 8 * 8 * 4)   // 117,760 B

__global__ __launch_bounds__(256, 1) void fused_rnn(
    const float* __restrict__ Wh0,   // [256][1024]
    const float* __restrict__ Wx1,   // [256][1024]
    const float* __restrict__ Wh1,   // [256][1024]
    const float* __restrict__ b1,    // [1024]
    float*       __restrict__ h1_out,
    float*       __restrict__ h2_out)
{
    extern __shared__ char smc[];
    __nv_bfloat16* sBhi = (__nv_bfloat16*)(smc + OFF_BHI);
    __nv_bfloat16* sBlo = (__nv_bfloat16*)(smc + OFF_BLO);
    float*         sPart = (float*)(smc + OFF_PART);

    const int t    = threadIdx.x;
    const int warp = t >> 5;
    const int lane = t & 31;
    const int kg0  = blockIdx.x * 8;
    const int c    = t & 7;
    const int b    = t >> 3;
    const int k    = (kg0 + c) >> 2;
    const bool owner = (t & 3) == 0;
    const unsigned base = lane & ~3u;
    const unsigned grid = gridDim.x;

    for (int idx = t; idx < 3 * 8 * NH; idx += 256) {
        int m   = idx >> 11;
        int rem = idx & 2047;
        int j   = rem >> 8;
        int kk  = rem & 255;
        const float* src = (m == 0) ? Wh0 : ((m == 1) ? Wx1 : Wh1);
        float x = src[(size_t)kk * NG + kg0 + j];
        __nv_bfloat16 hi = __float2bfloat16_rn(x);
        int row = m * 8 + j;
        sBhi[row * RPITCH + kk] = hi;
        sBlo[row * RPITCH + kk] = __float2bfloat16_rn(x - __bfloat162float(hi));
    }
    const float b1v = b1[kg0 + c];

    const uint32_t usm  = (uint32_t)__cvta_generic_to_shared(smc);
    const uint32_t uBhi = usm + OFF_BHI;
    const uint32_t uBlo = usm + OFF_BLO;
    const uint32_t uA0  = usm + OFF_A;
    const uint32_t uA1  = uA0 + PLANE_B;
    const uint32_t uA2  = uA1 + PLANE_B;
    const uint32_t uA3  = uA2 + PLANE_B;

    const int a_row = lane & 15;
    const int a_k   = (lane >> 4) * 8;
    const int b_row = (lane & 7) + ((lane >> 4) << 3);
    const int b_k   = ((lane >> 3) & 1) * 8;
    const int k0w   = warp * 32;

    float c1 = 0.f, c2 = 0.f;

    for (int r = 0; r <= SEQ; r++) {
        int s0 = (r < SEQ) ? r : SEQ - 1;
        float gx0v = g_gx[(size_t)s0 * BATCH * NG + (size_t)b * NG + kg0 + c];

        if (r > 0 && t == 0) {
            while (*(volatile unsigned*)&g_flag < (unsigned)r) { }
            __threadfence();
        }
        __syncthreads();

        {
            const __nv_bfloat16* gp[4] = { g_h1hi[r & 1], g_h1lo[r & 1],
                                           g_h2hi[r & 1], g_h2lo[r & 1] };
            #pragma unroll
            for (int p = 0; p < 4; p++) {
                __nv_bfloat16* sAp = (__nv_bfloat16*)(smc + OFF_A + p * PLANE_B);
                #pragma unroll
                for (int i = 0; i < 4; i++) {
                    int cc = t + i * 256;
                    int row = cc >> 5, c16 = cc & 31;
                    *(uint4*)&sAp[row * RPITCH + c16 * 8] =
                        __ldcg((const uint4*)(gp[p] + row * NH + c16 * 8));
                }
            }
        }
        __syncthreads();

        float z0a[2][4], z1a[2][4];
        #pragma unroll
        for (int m = 0; m < 2; m++)
            #pragma unroll
            for (int q = 0; q < 4; q++) { z0a[m][q] = 0.f; z1a[m][q] = 0.f; }

        #pragma unroll
        for (int kc = 0; kc < 2; kc++) {
            const int k0 = k0w + kc * 16;
            uint32_t ah1h[2][4], ah1l[2][4], ah2h[2][4], ah2l[2][4];
            #pragma unroll
            for (int m = 0; m < 2; m++) {
                uint32_t ro = (uint32_t)((m * 16 + a_row) * RPITCH + k0 + a_k) * 2;
                LDM_A(ah1h[m][0], ah1h[m][1], ah1h[m][2], ah1h[m][3], uA0 + ro);
                LDM_A(ah1l[m][0], ah1l[m][1], ah1l[m][2], ah1l[m][3], uA1 + ro);
                LDM_A(ah2h[m][0], ah2h[m][1], ah2h[m][2], ah2h[m][3], uA2 + ro);
                LDM_A(ah2l[m][0], ah2l[m][1], ah2l[m][2], ah2l[m][3], uA3 + ro);
            }
            uint32_t w0h[2], wxh[2], w1h[2], w0l[2], wxl[2], w1l[2];
            {
                uint32_t ro = (uint32_t)(b_row * RPITCH + k0 + b_k) * 2;
                uint32_t r0, r1, r2, r3;
                LDM_A(r0, r1, r2, r3, uBhi + ro);
                w0h[0] = r0; w0h[1] = r1; wxh[0] = r2; wxh[1] = r3;
                LDM_A(r0, r1, r2, r3, uBlo + ro);
                w0l[0] = r0; w0l[1] = r1; wxl[0] = r2; wxl[1] = r3;
                uint32_t ro2 = (uint32_t)((16 + b_row) * RPITCH + k0 + b_k) * 2;
                LDM_A(r0, r1, r2, r3, uBhi + ro2);
                w1h[0] = r0; w1h[1] = r1;
                LDM_A(r0, r1, r2, r3, uBlo + ro2);
                w1l[0] = r0; w1l[1] = r1;
            }
            #pragma unroll
            for (int m = 0; m < 2; m++) {
                MMA_BF16(z0a[m], ah1h[m], w0h);
                MMA_BF16(z0a[m], ah1h[m], w0l);
                MMA_BF16(z0a[m], ah1l[m], w0h);
                MMA_BF16(z1a[m], ah1h[m], wxh);
                MMA_BF16(z1a[m], ah1h[m], wxl);
                MMA_BF16(z1a[m], ah1l[m], wxh);
                MMA_BF16(z1a[m], ah2h[m], w1h);
                MMA_BF16(z1a[m], ah2h[m], w1l);
                MMA_BF16(z1a[m], ah2l[m], w1h);
            }
        }

        {
            const int g  = lane >> 2;
            const int t4 = lane & 3;
            #pragma unroll
            for (int m = 0; m < 2; m++) {
                int rowb = m * 16 + g;
                float* p0 = sPart + (0 * 32 + rowb) * 64 + (2 * t4) * 8 + warp;
                float* p1 = sPart + (1 * 32 + rowb) * 64 + (2 * t4) * 8 + warp;
                p0[0] = z0a[m][0]; p0[8] = z0a[m][1]; p0[512] = z0a[m][2]; p0[520] = z0a[m][3];
                p1[0] = z1a[m][0]; p1[8] = z1a[m][1]; p1[512] = z1a[m][2]; p1[520] = z1a[m][3];
            }
        }
        __syncthreads();

        float z0 = gx0v, z1 = b1v;
        {
            const float* q0 = sPart + b * 64 + c * 8;
            const float* q1 = sPart + (32 + b) * 64 + c * 8;
            float4 v0 = *(const float4*)q0, v1 = *(const float4*)(q0 + 4);
            z0 += v0.x + v0.y + v0.z + v0.w + v1.x + v1.y + v1.z + v1.w;
            float4 u0 = *(const float4*)q1, u1 = *(const float4*)(q1 + 4);
            z1 += u0.x + u0.y + u0.z + u0.w + u1.x + u1.y + u1.z + u1.w;
        }

        float zi0 = __shfl_sync(0xffffffffu, z0, base + 0);
        float zf0 = __shfl_sync(0xffffffffu, z0, base + 1);
        float zo0 = __shfl_sync(0xffffffffu, z0, base + 2);
        float zg0 = __shfl_sync(0xffffffffu, z0, base + 3);
        float zi1 = __shfl_sync(0xffffffffu, z1, base + 0);
        float zf1 = __shfl_sync(0xffffffffu, z1, base + 1);
        float zo1 = __shfl_sync(0xffffffffu, z1, base + 2);
        float zg1 = __shfl_sync(0xffffffffu, z1, base + 3);

        if (owner) {
            int np = (r + 1) & 1;
            if (r < SEQ) {
                float ig = 1.f / (1.f + __expf(-zi0));
                float fg = 1.f / (1.f + __expf(-zf0));
                float og = 1.f / (1.f + __expf(-zo0));
                float gg = tanhf(zg0);
                c1 = fg * c1 + ig * gg;
                float hn = og * tanhf(c1);
                __nv_bfloat16 hb = __float2bfloat16_rn(hn);
                g_h1hi[np][b * NH + k] = hb;
                g_h1lo[np][b * NH + k] = __float2bfloat16_rn(hn - __bfloat162float(hb));
                if (r == SEQ - 1) h1_out[b * NH + k] = hn;
            }
            if (r >= 1) {
                int s1 = r - 1;
                float ig = 1.f / (1.f + __expf(-zi1));
                float fg = 1.f / (1.f + __expf(-zf1));
                float og = 1.f / (1.f + __expf(-zo1));
                float gg = tanhf(zg1);
                c2 = fg * c2 + ig * gg;
                float hn = og * tanhf(c2);
                __nv_bfloat16 hb = __float2bfloat16_rn(hn);
                __nv_bfloat16 lb = __float2bfloat16_rn(hn - __bfloat162float(hb));
                g_h2hi[np][b * NH + k] = hb;
                g_h2lo[np][b * NH + k] = lb;
                size_t m = (size_t)s1 * BATCH + b;
                g_Ahi[m * NH + k] = hb;
                g_Alo[m * NH + k] = lb;
                if (s1 == SEQ - 1) h2_out[b * NH + k] = hn;
            }
        }

        if (r < SEQ) {
            __syncthreads();
            if (t == 0) {
                __threadfence();
                unsigned old = atomicAdd(&g_cnt, 1u);
                if (old == (unsigned)r * grid + grid - 1u)
                    atomicExch(&g_flag, (unsigned)(r + 1));
            }
        }
    }
}

// ---------------- bf16 split of decoder weights (scalar — proven) ----------------
__global__ __launch_bounds__(256) void conv_W(const float* __restrict__ W) {
    int i = blockIdx.x * blockDim.x + threadIdx.x;
    if (i < NVPAD * NH) {
        int v = i >> 8;
        float x = (v < NVOC) ? W[(size_t)v * NH + (i & 255)] : 0.f;
        __nv_bfloat16 hi = __float2bfloat16_rn(x);
        g_Whi[i] = hi;
        g_Wlo[i] = __float2bfloat16_rn(x - __bfloat162float(hi));
    }
}

// ---------------- tensor-core decoder GEMM (split-bf16; cp.async double-buffered) ----------------
// Dynamic smem: 2 stages x 4 tiles x (128 x 40 bf16 = 10240 B) = 81,920 B.
#define DTILE   10240
#define DSTAGE  (4 * DTILE)
#define DS_BYTES (2 * DSTAGE)

__global__ __launch_bounds__(256, 2) void gemm_dec_tc(
    const float* __restrict__ bias,
    float*       __restrict__ out)
{
    extern __shared__ char dsm[];

    const int t    = threadIdx.x;
    const int warp = t >> 5;
    const int lane = t & 31;
    const int m0   = blockIdx.y * 128;
    const int n0   = blockIdx.x * 128;
    const int wm   = warp >> 2;
    const int wn   = warp & 3;

    float acc[4][4][4];
    #pragma unroll
    for (int i = 0; i < 4; i++)
        #pragma unroll
        for (int j = 0; j < 4; j++)
            #pragma unroll
            for (int q = 0; q < 4; q++) acc[i][j][q] = 0.f;

    const uint32_t usm = (uint32_t)__cvta_generic_to_shared(dsm);

    const int a_row = (lane & 15);
    const int a_k   = (lane >> 4) * 8;
    const int b_row = (lane & 7) + ((lane >> 4) << 3);
    const int b_k   = ((lane >> 3) & 1) * 8;

    // per-thread load mapping (2 chunks x 4 tiles per k-chunk)
    int rowL[2], qL[2];
    #pragma unroll
    for (int h = 0; h < 2; h++) { int cc = t + h * 256; rowL[h] = cc >> 2; qL[h] = cc & 3; }

    // issue loads for k-chunk kc into stage s
    auto issue = [&](int kc, int s) {
        const int k0 = kc * 32;
        uint32_t sb = usm + (uint32_t)s * DSTAGE;
        #pragma unroll
        for (int h = 0; h < 2; h++) {
            int row = rowL[h], q = qL[h];
            uint32_t so = (uint32_t)(row * 40 + q * 8) * 2;
            size_t gA = (size_t)(m0 + row) * NH + k0 + q * 8;
            size_t gB = (size_t)(n0 + row) * NH + k0 + q * 8;
            CP_ASYNC16(sb + 0 * DTILE + so, g_Ahi + gA);
            CP_ASYNC16(sb + 1 * DTILE + so, g_Alo + gA);
            CP_ASYNC16(sb + 2 * DTILE + so, g_Whi + gB);
            CP_ASYNC16(sb + 3 * DTILE + so, g_Wlo + gB);
        }
        CP_COMMIT();
    };

    issue(0, 0);

    for (int kc = 0; kc < 8; kc++) {
        if (kc < 7) issue(kc + 1, (kc + 1) & 1);
        if (kc < 7) { CP_WAIT1(); } else { CP_WAIT0(); }
        __syncthreads();

        const uint32_t sb   = usm + (uint32_t)(kc & 1) * DSTAGE;
        const uint32_t bAhi = sb + 0 * DTILE;
        const uint32_t bAlo = sb + 1 * DTILE;
        const uint32_t bBhi = sb + 2 * DTILE;
        const uint32_t bBlo = sb + 3 * DTILE;

        #pragma unroll
        for (int ks = 0; ks < 32; ks += 16) {
            uint32_t af[4][4];
            uint32_t bh[4][2], bl[4][2];

            #pragma unroll
            for (int nh = 0; nh < 2; nh++) {
                int roff = (wn * 32 + nh * 16 + b_row) * 40 + ks + b_k;
                uint32_t r0, r1, r2, r3;
                LDM_A(r0, r1, r2, r3, bBhi + roff * 2);
                bh[2*nh][0] = r0; bh[2*nh][1] = r1;
                bh[2*nh+1][0] = r2; bh[2*nh+1][1] = r3;
                LDM_A(r0, r1, r2, r3, bBlo + roff * 2);
                bl[2*nh][0] = r0; bl[2*nh][1] = r1;
                bl[2*nh+1][0] = r2; bl[2*nh+1][1] = r3;
            }
            #pragma unroll
            for (int mi = 0; mi < 4; mi++) {
                int roff = (wm * 64 + mi * 16 + a_row) * 40 + ks + a_k;
                LDM_A(af[mi][0], af[mi][1], af[mi][2], af[mi][3], bAhi + roff * 2);
            }
            #pragma unroll
            for (int mi = 0; mi < 4; mi++)
                #pragma unroll
                for (int ni = 0; ni < 4; ni++) {
                    MMA_BF16(acc[mi][ni], af[mi], bh[ni]);
                    MMA_BF16(acc[mi][ni], af[mi], bl[ni]);
                }
            #pragma unroll
            for (int mi = 0; mi < 4; mi++) {
                int roff = (wm * 64 + mi * 16 + a_row) * 40 + ks + a_k;
                LDM_A(af[mi][0], af[mi][1], af[mi][2], af[mi][3], bAlo + roff * 2);
            }
            #pragma unroll
            for (int mi = 0; mi < 4; mi++)
                #pragma unroll
                for (int ni = 0; ni < 4; ni++)
                    MMA_BF16(acc[mi][ni], af[mi], bh[ni]);
        }
        __syncthreads();
    }

    const int g  = lane >> 2;
    const int t4 = lane & 3;
    #pragma unroll
    for (int mi = 0; mi < 4; mi++) {
        #pragma unroll
        for (int ni = 0; ni < 4; ni++) {
            int col = n0 + wn * 32 + ni * 8 + t4 * 2;
            if (col < NVOC) {
                float b0 = bias[col], b1 = bias[col + 1];
                int row0 = m0 + wm * 64 + mi * 16 + g;
                float2 v0 = make_float2(acc[mi][ni][0] + b0, acc[mi][ni][1] + b1);
                float2 v1 = make_float2(acc[mi][ni][2] + b0, acc[mi][ni][3] + b1);
                *(float2*)(out + (size_t)row0 * NVOC + col) = v0;
                *(float2*)(out + (size_t)(row0 + 8) * NVOC + col) = v1;
            }
        }
    }
}

// ---------------- launch ----------------
extern "C" void kernel_launch(void* const* d_in, const int* in_sizes, int n_in,
                              void* d_out, int out_size) {
    const int*   tokens  = (const int*)  d_in[0];
    const float* embed_W = (const float*)d_in[1];
    const float* Wx0     = (const float*)d_in[2];
    const float* Wh0     = (const float*)d_in[3];
    const float* b0      = (const float*)d_in[4];
    const float* Wx1     = (const float*)d_in[5];
    const float* Wh1     = (const float*)d_in[6];
    const float* b1      = (const float*)d_in[7];
    const float* dec_W   = (const float*)d_in[8];
    const float* dec_b   = (const float*)d_in[9];
    (void)in_sizes; (void)n_in;

    float* out    = (float*)d_out;
    float* h1_out = out + (size_t)out_size - 2 * BATCH * NH;
    float* h2_out = out + (size_t)out_size - 1 * BATCH * NH;

    static bool attr_done = false;
    if (!attr_done) {
        cudaFuncSetAttribute(fused_rnn, cudaFuncAttributeMaxDynamicSharedMemorySize, RS_BYTES);
        cudaFuncSetAttribute(gemm_dec_tc, cudaFuncAttributeMaxDynamicSharedMemorySize, DS_BYTES);
        attr_done = true;
    }

    conv_W<<<(NVPAD * NH + 255) / 256, 256>>>(dec_W);
    init_state<<<16, 256>>>();
    gemm_gx<<<dim3(8, 64), 256>>>(embed_W, tokens, Wx0, b0);
    fused_rnn<<<128, 256, RS_BYTES>>>(Wh0, Wx1, Wh1, b1, h1_out, h2_out);
    gemm_dec_tc<<<dim3(79, 64), 256, DS_BYTES>>>(dec_b, out);
}